// round 11
// baseline (speedup 1.0000x reference)
#include <cuda_runtime.h>
#include <cstdint>

// Problem constants (fixed shapes from the reference: B=16, N=2048, D=64)
#define BATCH 16
#define NN    2048
#define DD    64

#define BM 128          // rows per block
#define BK 16           // K-tile
#define BN 64           // = D, full width
#define AS_STRIDE 132   // BM + 4 pad: keeps 16B alignment for compute LDS.128
#define NTHREADS 256
#define NITER (NN / BK) // 128 K-tiles

typedef unsigned long long u64;

__device__ __forceinline__ void ffma2(u64& d, u64 a, u64 b) {
    // d = a * b + d, elementwise on packed fp32 pairs (PTX-only on sm_103a)
    asm("fma.rn.f32x2 %0, %1, %2, %0;" : "+l"(d) : "l"(a), "l"(b));
}
__device__ __forceinline__ u64 fadd2(u64 a, u64 b) {
    u64 r;
    asm("add.rn.f32x2 %0, %1, %2;" : "=l"(r) : "l"(a), "l"(b));
    return r;
}
__device__ __forceinline__ float lo2(u64 v) {
    return __uint_as_float((unsigned)(v & 0xffffffffull));
}
__device__ __forceinline__ float hi2(u64 v) {
    return __uint_as_float((unsigned)(v >> 32));
}
__device__ __forceinline__ float rcp_fast(float x) {
    // single MUFU.RCP; ~1e-7 rel error, gate is 1e-3
    float r;
    asm("rcp.approx.f32 %0, %1;" : "=f"(r) : "f"(x));
    return r;
}

__global__ __launch_bounds__(NTHREADS, 2)
void gcn_fused_kernel(const float* __restrict__ nodes,
                      const float* __restrict__ edges,
                      float* __restrict__ out)
{
    // As: k-major, rows contiguous -> compute reads row pairs as u64 directly.
    // Bs: stored DUPLICATED (x,x,y,y,z,z,w,w) so a compute LDS.128 yields two
    //     ready f32x2 broadcast pairs with zero MOVs in the inner loop.
    __shared__ float As[2][BK][AS_STRIDE];
    __shared__ float Bs[2][BK][BN * 2];
    __shared__ float rowsum[BM];

    const int tid    = threadIdx.x;
    const int b      = blockIdx.y;
    const int row0   = blockIdx.x * BM;

    const float* __restrict__ A = edges + (size_t)b * NN * NN;
    const float* __restrict__ X = nodes + (size_t)b * NN * DD;
    float* __restrict__       O = out   + (size_t)b * NN * DD;

    // --- loader thread mapping ---
    // A tile: 128 rows x 16 k = 512 float4; 2 per thread.
    // The 4 threads loading row r are lanes 4r..4r+3 (same warp) ->
    // rowsum fold is an intra-warp shuffle, no atomics, no zero-init.
    const int rowA0 = tid >> 2;          // 0..63
    const int rowA1 = rowA0 + 64;        // 64..127
    const int kq    = (tid & 3) * 4;     // k offset of this thread's float4
    // B tile: 16 rows x 64 n = 256 float4 source; 1 per thread (2 dup stores)
    const int rowB  = tid >> 4;          // 0..15
    const int nB    = (tid & 15) * 4;    // 0..60

    // --- compute thread mapping ---
    const int tn = tid & 15;             // col group: cols tn*4 .. tn*4+3
    const int tm = tid >> 4;             // row group: rows tm*8 .. tm*8+7

    u64 acc[4][4];                       // [row-pair][col], packed f32x2
    #pragma unroll
    for (int i = 0; i < 4; ++i)
        #pragma unroll
        for (int j = 0; j < 4; ++j) acc[i][j] = 0ull;

    // rowsum partials kept as packed f32x2 (horizontal fold deferred to end)
    u64 rsp0 = 0ull, rsp1 = 0ull;

    const float* pA0 = A + (size_t)(row0 + rowA0) * NN + kq;
    const float* pA1 = A + (size_t)(row0 + rowA1) * NN + kq;
    const float* pB  = X + (size_t)rowB * DD + nB;

    // stage helper: A transposed to k-major; B duplicated for f32x2 broadcast;
    // rowsum partials accumulated with packed adds (2 fadd2 per float4).
    auto stage = [&](int buf, const float4& fa0, const float4& fa1,
                     const float4& fb) {
        As[buf][kq + 0][rowA0] = fa0.x;  As[buf][kq + 1][rowA0] = fa0.y;
        As[buf][kq + 2][rowA0] = fa0.z;  As[buf][kq + 3][rowA0] = fa0.w;
        As[buf][kq + 0][rowA1] = fa1.x;  As[buf][kq + 1][rowA1] = fa1.y;
        As[buf][kq + 2][rowA1] = fa1.z;  As[buf][kq + 3][rowA1] = fa1.w;
        const u64* q0 = reinterpret_cast<const u64*>(&fa0);
        const u64* q1 = reinterpret_cast<const u64*>(&fa1);
        rsp0 = fadd2(rsp0, fadd2(q0[0], q0[1]));
        rsp1 = fadd2(rsp1, fadd2(q1[0], q1[1]));
        float4 d0 = make_float4(fb.x, fb.x, fb.y, fb.y);
        float4 d1 = make_float4(fb.z, fb.z, fb.w, fb.w);
        *reinterpret_cast<float4*>(&Bs[buf][rowB][2 * nB])     = d0;
        *reinterpret_cast<float4*>(&Bs[buf][rowB][2 * nB + 4]) = d1;
    };

    auto compute = [&](int buf) {
        #pragma unroll
        for (int k = 0; k < BK; ++k) {
            ulonglong2 a01 = *reinterpret_cast<const ulonglong2*>(
                &As[buf][k][tm * 8]);                 // (A[r0],A[r1]) pairs
            ulonglong2 a23 = *reinterpret_cast<const ulonglong2*>(
                &As[buf][k][tm * 8 + 4]);
            ulonglong2 b01 = *reinterpret_cast<const ulonglong2*>(
                &Bs[buf][k][tn * 8]);                 // (bx,bx),(by,by)
            ulonglong2 b23 = *reinterpret_cast<const ulonglong2*>(
                &Bs[buf][k][tn * 8 + 4]);             // (bz,bz),(bw,bw)

            ffma2(acc[0][0], a01.x, b01.x); ffma2(acc[0][1], a01.x, b01.y);
            ffma2(acc[0][2], a01.x, b23.x); ffma2(acc[0][3], a01.x, b23.y);
            ffma2(acc[1][0], a01.y, b01.x); ffma2(acc[1][1], a01.y, b01.y);
            ffma2(acc[1][2], a01.y, b23.x); ffma2(acc[1][3], a01.y, b23.y);
            ffma2(acc[2][0], a23.x, b01.x); ffma2(acc[2][1], a23.x, b01.y);
            ffma2(acc[2][2], a23.x, b23.x); ffma2(acc[2][3], a23.x, b23.y);
            ffma2(acc[3][0], a23.y, b01.x); ffma2(acc[3][1], a23.y, b01.y);
            ffma2(acc[3][2], a23.y, b23.x); ffma2(acc[3][3], a23.y, b23.y);
        }
    };

    // prologue: load + stage tile 0
    {
        float4 fa0 = *reinterpret_cast<const float4*>(pA0);
        float4 fa1 = *reinterpret_cast<const float4*>(pA1);
        float4 fb  = *reinterpret_cast<const float4*>(pB);
        stage(0, fa0, fa1, fb);
    }
    __syncthreads();

    // main loop: NITER-1 full iterations [load i+1 | compute i | stage i+1],
    // then a final compute-only step. unroll 2 keeps cur/nxt compile-time.
    int cur = 0;
    #pragma unroll 2
    for (int it = 0; it < NITER - 1; ++it) {
        const int kt = (it + 1) * BK;
        // issue next tile's global loads first (in flight during compute)
        float4 fa0 = *reinterpret_cast<const float4*>(pA0 + kt);
        float4 fa1 = *reinterpret_cast<const float4*>(pA1 + kt);
        float4 fb  = *reinterpret_cast<const float4*>(pB + (size_t)kt * DD);

        compute(cur);

        const int nxt = cur ^ 1;
        stage(nxt, fa0, fa1, fb);
        __syncthreads();
        cur = nxt;
    }

    // prefetch the epilogue X rows BEFORE the last compute so their DRAM/L2
    // latency is hidden under the final 16-k FFMA2 block (independent data).
    float4 xl[4], xh[4];
    #pragma unroll
    for (int rp = 0; rp < 4; ++rp) {
        const int rl = tm * 8 + 2 * rp;
        xl[rp] = *reinterpret_cast<const float4*>(
            &X[(size_t)(row0 + rl) * DD + tn * 4]);
        xh[rp] = *reinterpret_cast<const float4*>(
            &X[(size_t)(row0 + rl + 1) * DD + tn * 4]);
    }

    compute(cur);

    // fold row-sum partials: horizontal pair fold, then butterfly shuffle
    // over the low 2 lane bits; one lane per row writes the final sum.
    float rs0 = lo2(rsp0) + hi2(rsp0);
    float rs1 = lo2(rsp1) + hi2(rsp1);
    rs0 += __shfl_xor_sync(0xffffffffu, rs0, 1);
    rs0 += __shfl_xor_sync(0xffffffffu, rs0, 2);
    rs1 += __shfl_xor_sync(0xffffffffu, rs1, 1);
    rs1 += __shfl_xor_sync(0xffffffffu, rs1, 2);
    if ((tid & 3) == 0) {
        rowsum[rowA0] = rs0;
        rowsum[rowA1] = rs1;
    }
    __syncthreads();

    // epilogue: out = (acc + X[row]) / (1 + rowsum[row]); denom >= 1 -> no NaN.
    // rcp.approx (~1e-7 rel err) is far inside the 1e-3 gate.
    #pragma unroll
    for (int rp = 0; rp < 4; ++rp) {
        const int rl = tm * 8 + 2 * rp;
        const int rh = rl + 1;
        const float invl = rcp_fast(1.0f + rowsum[rl]);
        const float invh = rcp_fast(1.0f + rowsum[rh]);

        float4 ol, oh;
        ol.x = (lo2(acc[rp][0]) + xl[rp].x) * invl;
        ol.y = (lo2(acc[rp][1]) + xl[rp].y) * invl;
        ol.z = (lo2(acc[rp][2]) + xl[rp].z) * invl;
        ol.w = (lo2(acc[rp][3]) + xl[rp].w) * invl;
        oh.x = (hi2(acc[rp][0]) + xh[rp].x) * invh;
        oh.y = (hi2(acc[rp][1]) + xh[rp].y) * invh;
        oh.z = (hi2(acc[rp][2]) + xh[rp].z) * invh;
        oh.w = (hi2(acc[rp][3]) + xh[rp].w) * invh;

        *reinterpret_cast<float4*>(&O[(size_t)(row0 + rl) * DD + tn * 4]) = ol;
        *reinterpret_cast<float4*>(&O[(size_t)(row0 + rh) * DD + tn * 4]) = oh;
    }
}

extern "C" void kernel_launch(void* const* d_in, const int* in_sizes, int n_in,
                              void* d_out, int out_size)
{
    // Resolve input order from element counts instead of trusting position:
    // nodes = B*N*D = 2,097,152 elems; edges = B*N*N = 67,108,864 elems.
    const float* nodes;
    const float* edges;
    if (in_sizes[0] == BATCH * NN * DD) {
        nodes = (const float*)d_in[0];
        edges = (const float*)d_in[1];
    } else {
        edges = (const float*)d_in[0];
        nodes = (const float*)d_in[1];
    }
    float* out = (float*)d_out;                   // (16, 2048, 64) float32

    dim3 grid(NN / BM, BATCH);   // (16, 16) = 256 CTAs, one wave @ occ 2
    gcn_fused_kernel<<<grid, NTHREADS>>>(nodes, edges, out);
}

// round 17
// speedup vs baseline: 3.4997x; 3.4997x over previous
#include <cuda_runtime.h>
#include <cuda_fp16.h>
#include <cstdint>

// Shapes fixed by the reference: B=16, N=2048, D=64
#define BATCH 16
#define NN    2048
#define DD    64
#define BM    128             // rows per CTA
#define CK    64              // k per chunk (64 f16 = 128B = one SW128 row)
#define NCHUNK (NN / CK)      // 32
#define T_MMA 128             // 4 warps: 2(m) x 2(n) grid, warp = m64 x n32
#define T_TR  256

#define SW128(o) ((o) ^ (((o) >> 3) & 0x70))

typedef unsigned long long u64;

// f16 transposed nodes: [b][d][k]  (4 MB static device scratch)
__device__ __half g_xt[(size_t)BATCH * DD * NN];

// ---------------- helpers ----------------
__device__ __forceinline__ uint32_t smem_u32(const void* p) {
    uint32_t a;
    asm("{ .reg .u64 t; cvta.to.shared.u64 t, %1; cvt.u32.u64 %0, t; }"
        : "=r"(a) : "l"(p));
    return a;
}
// pack two fp32 -> f16x2, lo first in memory order
__device__ __forceinline__ uint32_t pk16(float lo, float hi) {
    uint32_t r;
    asm("cvt.rn.f16x2.f32 %0, %1, %2;" : "=r"(r) : "f"(hi), "f"(lo));
    return r;
}
__device__ __forceinline__ u64 fadd2(u64 a, u64 b) {
    u64 r;
    asm("add.rn.f32x2 %0, %1, %2;" : "=l"(r) : "l"(a), "l"(b));
    return r;
}
__device__ __forceinline__ float lo2(u64 v) {
    return __uint_as_float((unsigned)(v & 0xffffffffull));
}
__device__ __forceinline__ float hi2(u64 v) {
    return __uint_as_float((unsigned)(v >> 32));
}
__device__ __forceinline__ float rcp_fast(float x) {
    float r;
    asm("rcp.approx.f32 %0, %1;" : "=f"(r) : "f"(x));
    return r;
}
__device__ __forceinline__ void ldsm_x4(uint32_t* r, uint32_t addr) {
    asm volatile("ldmatrix.sync.aligned.m8n8.x4.shared.b16 {%0,%1,%2,%3}, [%4];"
                 : "=r"(r[0]), "=r"(r[1]), "=r"(r[2]), "=r"(r[3]) : "r"(addr));
}
__device__ __forceinline__ void mma16816(float* d, const uint32_t* a,
                                         uint32_t b0, uint32_t b1) {
    asm volatile("mma.sync.aligned.m16n8k16.row.col.f32.f16.f16.f32 "
                 "{%0,%1,%2,%3}, {%4,%5,%6,%7}, {%8,%9}, {%0,%1,%2,%3};"
                 : "+f"(d[0]), "+f"(d[1]), "+f"(d[2]), "+f"(d[3])
                 : "r"(a[0]), "r"(a[1]), "r"(a[2]), "r"(a[3]), "r"(b0), "r"(b1));
}

// ---------------- kernel 1: nodes (fp32 [b][k][d]) -> f16 X^T [b][d][k] ----
__global__ __launch_bounds__(T_TR)
void transpose_nodes_k(const float* __restrict__ nodes) {
    __shared__ float tile[64][65];
    const int kc = blockIdx.x, b = blockIdx.y;
    const int t = threadIdx.x;
    {
        const int j = t >> 2, dq = (t & 3) * 16;
        const float* src = nodes + ((size_t)b * NN + (size_t)kc * 64 + j) * DD + dq;
        #pragma unroll
        for (int q = 0; q < 4; ++q) {
            float4 v = *reinterpret_cast<const float4*>(src + q * 4);
            tile[j][dq + q * 4 + 0] = v.x;  tile[j][dq + q * 4 + 1] = v.y;
            tile[j][dq + q * 4 + 2] = v.z;  tile[j][dq + q * 4 + 3] = v.w;
        }
    }
    __syncthreads();
    {
        const int d = t >> 2, kq = (t & 3) * 16;
        uint32_t h[8];
        #pragma unroll
        for (int i = 0; i < 8; ++i)
            h[i] = pk16(tile[kq + 2 * i][d], tile[kq + 2 * i + 1][d]);
        __half* dst = g_xt + ((size_t)b * DD + d) * NN + (size_t)kc * 64 + kq;
        *reinterpret_cast<uint4*>(dst)     = make_uint4(h[0], h[1], h[2], h[3]);
        *reinterpret_cast<uint4*>(dst + 8) = make_uint4(h[4], h[5], h[6], h[7]);
    }
}

// ---------------- kernel 2: fused (A+I)X / rowsum via mma.sync (HMMA) ------
__global__ __launch_bounds__(T_MMA, 2)
void gcn_mma_kernel(const float* __restrict__ nodes,
                    const float* __restrict__ edges,
                    float* __restrict__ out) {
    // A tile: 128 rows x 64 f16 = one SW128 128B row each -> 16 KB
    // B tile (X^T chunk): 64 rows x 64 f16 -> 8 KB
    __shared__ __align__(1024) uint8_t sA[BM * 128];
    __shared__ __align__(1024) uint8_t sB[DD * 128];
    __shared__ float rowsum[BM];

    const int tid  = threadIdx.x;
    const int wid  = tid >> 5, lane = tid & 31;
    const int wm   = wid & 1;            // m half: rows wm*64
    const int wn   = wid >> 1;           // n half: cols wn*32
    const int b    = blockIdx.y;
    const int row0 = blockIdx.x * BM;

    const float* __restrict__ A = edges + (size_t)b * NN * NN;

    // staging map: thread t handles row t/2, k-half t&1
    const int srow = tid >> 1, sh = tid & 1;        // srow 0..63
    const int arow2 = srow + 64;                    // A rows 64..127
    const float*  pa  = A + (size_t)(row0 + srow)  * NN + sh * 32;
    const float*  pa2 = A + (size_t)(row0 + arow2) * NN + sh * 32;
    const __half* px  = g_xt + ((size_t)b * DD + srow) * NN + sh * 32;

    float acc[4][4][4];
    #pragma unroll
    for (int i = 0; i < 4; ++i)
        #pragma unroll
        for (int j = 0; j < 4; ++j)
            #pragma unroll
            for (int c = 0; c < 4; ++c) acc[i][j][c] = 0.0f;

    u64 rsp1 = 0ull, rsp2 = 0ull;        // fp32x2 rowsum partials (rows srow, srow+64)

    const uint32_t sa_u = smem_u32(sA), sb_u = smem_u32(sB);

    // prefetch chunk 0
    float4 ra1[8], ra2[8]; uint4 rb[4];
    #pragma unroll
    for (int q = 0; q < 8; ++q) {
        ra1[q] = *reinterpret_cast<const float4*>(pa  + q * 4);
        ra2[q] = *reinterpret_cast<const float4*>(pa2 + q * 4);
    }
    #pragma unroll
    for (int q = 0; q < 4; ++q)
        rb[q] = *reinterpret_cast<const uint4*>(
            reinterpret_cast<const uint8_t*>(px) + q * 16);

    for (int c = 0; c < NCHUNK; ++c) {
        // ---- stage chunk c (regs -> smem), accumulate exact fp32 rowsum ----
        {
            const uint32_t base1 = (uint32_t)srow  * 128 + (uint32_t)sh * 64;
            const uint32_t base2 = (uint32_t)arow2 * 128 + (uint32_t)sh * 64;
            #pragma unroll
            for (int q = 0; q < 4; ++q) {
                uint4 v1, v2;
                v1.x = pk16(ra1[2*q].x,   ra1[2*q].y);
                v1.y = pk16(ra1[2*q].z,   ra1[2*q].w);
                v1.z = pk16(ra1[2*q+1].x, ra1[2*q+1].y);
                v1.w = pk16(ra1[2*q+1].z, ra1[2*q+1].w);
                v2.x = pk16(ra2[2*q].x,   ra2[2*q].y);
                v2.y = pk16(ra2[2*q].z,   ra2[2*q].w);
                v2.z = pk16(ra2[2*q+1].x, ra2[2*q+1].y);
                v2.w = pk16(ra2[2*q+1].z, ra2[2*q+1].w);
                *reinterpret_cast<uint4*>(sA + SW128(base1 + q * 16)) = v1;
                *reinterpret_cast<uint4*>(sA + SW128(base2 + q * 16)) = v2;
                const u64* q1 = reinterpret_cast<const u64*>(&ra1[2*q]);
                const u64* q2 = reinterpret_cast<const u64*>(&ra2[2*q]);
                rsp1 = fadd2(rsp1, fadd2(q1[0], q1[1]));
                rsp1 = fadd2(rsp1, fadd2(q1[2], q1[3]));
                rsp2 = fadd2(rsp2, fadd2(q2[0], q2[1]));
                rsp2 = fadd2(rsp2, fadd2(q2[2], q2[3]));
            }
            const uint32_t bbase = (uint32_t)srow * 128 + (uint32_t)sh * 64;
            #pragma unroll
            for (int q = 0; q < 4; ++q)
                *reinterpret_cast<uint4*>(sB + SW128(bbase + q * 16)) = rb[q];
        }
        __syncthreads();

        // ---- prefetch chunk c+1 (in flight during compute) ----
        if (c + 1 < NCHUNK) {
            const float*  pan1 = pa  + (size_t)(c + 1) * CK;
            const float*  pan2 = pa2 + (size_t)(c + 1) * CK;
            const __half* pxn  = px  + (size_t)(c + 1) * CK;
            #pragma unroll
            for (int q = 0; q < 8; ++q) {
                ra1[q] = *reinterpret_cast<const float4*>(pan1 + q * 4);
                ra2[q] = *reinterpret_cast<const float4*>(pan2 + q * 4);
            }
            #pragma unroll
            for (int q = 0; q < 4; ++q)
                rb[q] = *reinterpret_cast<const uint4*>(
                    reinterpret_cast<const uint8_t*>(pxn) + q * 16);
        }

        // ---- compute: 4 k-frags x (4 A-ldmatrix + 2 B-ldmatrix + 16 mma) ----
        {
            const int lr = lane & 7;
            const int g1 = (lane >> 3) & 1;      // +8 rows
            const int g2 = (lane >> 4) & 1;      // +8 k cols (16B)
            #pragma unroll
            for (int kf = 0; kf < 4; ++kf) {
                const uint32_t kb = (uint32_t)kf * 32 + (uint32_t)g2 * 16;
                uint32_t af[4][4];
                #pragma unroll
                for (int mt = 0; mt < 4; ++mt) {
                    const uint32_t r = (uint32_t)(wm * 64 + mt * 16 + lr + g1 * 8);
                    ldsm_x4(af[mt], sa_u + SW128(r * 128 + kb));
                }
                uint32_t bf[2][4];
                #pragma unroll
                for (int np = 0; np < 2; ++np) {
                    const uint32_t n = (uint32_t)(wn * 32 + np * 16 + lr + g1 * 8);
                    ldsm_x4(bf[np], sb_u + SW128(n * 128 + kb));
                }
                #pragma unroll
                for (int mt = 0; mt < 4; ++mt)
                    #pragma unroll
                    for (int nt = 0; nt < 4; ++nt) {
                        const int np = nt >> 1, ix = nt & 1;
                        mma16816(acc[mt][nt], af[mt], bf[np][ix], bf[np][ix + 2]);
                    }
            }
        }
        __syncthreads();
    }

    // ---- exact fp32 rowsum fold: pair (t, t^1) share a row ----
    {
        float rs1 = lo2(rsp1) + hi2(rsp1);
        float rs2 = lo2(rsp2) + hi2(rsp2);
        rs1 += __shfl_xor_sync(0xffffffffu, rs1, 1);
        rs2 += __shfl_xor_sync(0xffffffffu, rs2, 1);
        if (sh == 0) { rowsum[srow] = rs1; rowsum[arow2] = rs2; }
    }
    __syncthreads();

    // ---- epilogue: out = (acc + X) * rcp(1 + rowsum) ----
    {
        const float* Xb = nodes + ((size_t)b * NN + row0) * DD;
        float*       Ob = out   + ((size_t)b * NN + row0) * DD;
        #pragma unroll
        for (int mt = 0; mt < 4; ++mt) {
            const int r = wm * 64 + mt * 16 + (lane >> 2);
            const float inv0 = rcp_fast(1.0f + rowsum[r]);
            const float inv1 = rcp_fast(1.0f + rowsum[r + 8]);
            const float* x0 = Xb + (size_t)r * DD;
            const float* x1 = Xb + (size_t)(r + 8) * DD;
            float* o0 = Ob + (size_t)r * DD;
            float* o1 = Ob + (size_t)(r + 8) * DD;
            #pragma unroll
            for (int nt = 0; nt < 4; ++nt) {
                const int col = wn * 32 + nt * 8 + (lane & 3) * 2;
                const float2 xa  = *reinterpret_cast<const float2*>(x0 + col);
                const float2 xb2 = *reinterpret_cast<const float2*>(x1 + col);
                float2 oa, ob;
                oa.x = (acc[mt][nt][0] + xa.x)  * inv0;
                oa.y = (acc[mt][nt][1] + xa.y)  * inv0;
                ob.x = (acc[mt][nt][2] + xb2.x) * inv1;
                ob.y = (acc[mt][nt][3] + xb2.y) * inv1;
                *reinterpret_cast<float2*>(o0 + col) = oa;
                *reinterpret_cast<float2*>(o1 + col) = ob;
            }
        }
    }
}

extern "C" void kernel_launch(void* const* d_in, const int* in_sizes, int n_in,
                              void* d_out, int out_size) {
    // Resolve input order from element counts (nodes = 2,097,152; edges = 67,108,864)
    const float* nodes;
    const float* edges;
    if (in_sizes[0] == BATCH * NN * DD) {
        nodes = (const float*)d_in[0];
        edges = (const float*)d_in[1];
    } else {
        edges = (const float*)d_in[0];
        nodes = (const float*)d_in[1];
    }
    float* out = (float*)d_out;

    transpose_nodes_k<<<dim3(NN / 64, BATCH), T_TR>>>(nodes);
    gcn_mma_kernel<<<dim3(NN / BM, BATCH), T_MMA>>>(nodes, edges, out);
}